// round 12
// baseline (speedup 1.0000x reference)
#include <cuda_runtime.h>
#include <cuda_bf16.h>
#include <math.h>
#include <complex>
#include <algorithm>

// ---------------- static problem shape ----------------
#define MUL    16
#define NCFG   64
#define NATOM  64
#define NNODES 4096
#define NPAIRS 262144
#define CROW   2600   // padded floats per node-pair row of g_C

// ---------------- device scratch (no allocation allowed) ----------------
// Row-pair-interleaved C: g_C[np*CROW + (kg*144 + b2)*2 + par]
__device__ float g_C[(size_t)2048 * CROW];
// planar irr: g_irr[k*NPAIRS + e]
__device__ float g_irr[(size_t)9 * NPAIRS];

struct QParams  { float q[81];  };   // QCART[k][3][3]
struct FoldParams { float cf[724]; };// cell-ordered fold coefficients (slices padded to 4)

// ---------------- f32x2 packed-math helpers ----------------
typedef unsigned long long u64t;
__device__ __forceinline__ u64t pk2(float lo, float hi){
    u64t r; asm("mov.b64 %0, {%1,%2};" : "=l"(r) : "f"(lo), "f"(hi)); return r;
}
__device__ __forceinline__ void fma2(u64t &d, u64t a, u64t b){
    asm("fma.rn.f32x2 %0, %1, %2, %0;" : "+l"(d) : "l"(a), "l"(b));
}
__device__ __forceinline__ void upk2(float &lo, float &hi, u64t v){
    asm("mov.b64 {%0,%1}, %2;" : "=f"(lo), "=f"(hi) : "l"(v));
}
__device__ __forceinline__ float dot4(float4 a, float4 b){
    return a.x*b.x + a.y*b.y + a.z*b.z + a.w*b.w;
}

// ==================================================================
// K1: per-node C build, cell-streamed, CELL-HALVED for occupancy.
// 512 blocks x 256 threads, 8 nodes/block.
// thread = (h = tid>>7, nl = (tid>>4)&7, v = tid&15).
//   h=0: cells {c02, c21, c22}  (cost ~804)
//   h=1: cells {c00, c01, c10, c11, c12, c20}  (cost ~800)
// smem: [cf 724][wsT 4800][xT 8*148][stage 4np*2592] = 17076 fl = 68304 B
// 3 blocks/SM -> 24 warps/SM.
// ==================================================================
#define K1_CF    0
#define K1_WS    724
#define K1_XT    (724 + 4800)
#define K1_STAGE (724 + 4800 + 1184)
#define SMEM_K1  ((724 + 4800 + 1184 + 10368) * 4)

// one (lo,l2) cell: accumulate out[jd*kd], then write to stage.
// CKG0 = absolute kg base for this lo (0 / 1 / 4).
template<int L2, int LO, int NP, int P0, int P1, int P2, int CFB, int CKG0>
__device__ __forceinline__ void do_cell(const float* __restrict__ xb,
                                        const float* __restrict__ wsT,
                                        const float* __restrict__ cfS,
                                        float* __restrict__ cst,
                                        const int v)
{
    constexpr int jd = 2*L2+1, kd = 2*LO+1;
    constexpr int S  = (jd*kd + 3) & ~3;
    constexpr int PLL[3] = {P0, P1, P2};
    constexpr int PD [15] = {1,3,5,1,3,3,3,5,5,1,5,3,3,5,5};
    constexpr int PFB[15] = {0,16,64,0,16,16,16,64,64,0,64,16,16,64,64};
    constexpr int L2B[3] = {0,16,64};

    float out[jd*kd];
    #pragma unroll
    for (int q = 0; q < jd*kd; q++) out[q] = 0.f;

    int slice = 0;
    #pragma unroll
    for (int pp = 0; pp < NP; pp++) {
        const int p = PLL[pp];
        const float4* w4 = (const float4*)(wsT + p*320 + v*20);
        const float4 w0 = w4[0], w1 = w4[1], w2 = w4[2], w3v = w4[3];
        #pragma unroll
        for (int i = 0; i < PD[PLL[pp]]; i++) {
            const float4* xr = (const float4*)(xb + PFB[PLL[pp]] + i*16);
            const float t = dot4(w0,xr[0]) + dot4(w1,xr[1])
                          + dot4(w2,xr[2]) + dot4(w3v,xr[3]);
            const int co = CFB + slice*S;
            #pragma unroll
            for (int g = 0; g < S/4; g++) {
                const float4 c4 = *(const float4*)(cfS + co + g*4);
                const float cc[4] = {c4.x, c4.y, c4.z, c4.w};
                #pragma unroll
                for (int l = 0; l < 4; l++) {
                    constexpr int JK = jd*kd;
                    const int lin = g*4 + l;
                    if (lin < JK) out[lin] += cc[l]*t;
                }
            }
            slice++;
        }
    }
    #pragma unroll
    for (int j = 0; j < jd; j++)
        #pragma unroll
        for (int k = 0; k < kd; k++)
            cst[((CKG0 + k)*144 + L2B[L2] + v*jd + j)*2] = out[j*kd + k];
}

__global__ __launch_bounds__(256, 3) void k1_buildC(const float* __restrict__ feats,
                                                    const float* __restrict__ tpw,
                                                    FoldParams fp)
{
    extern __shared__ float sm1[];
    float* cfS   = sm1 + K1_CF;
    float* wsT   = sm1 + K1_WS;
    float* xT    = sm1 + K1_XT;
    float* stage = sm1 + K1_STAGE;
    const int tid = threadIdx.x;
    const int nbase = blockIdx.x * 8;

    for (int idx = tid; idx < 3840; idx += 256) {
        const int p = idx >> 8, r = idx & 255, u = r >> 4, vv = r & 15;
        wsT[p*320 + vv*20 + u] = tpw[idx];
    }
    for (int idx = tid; idx < 8*144; idx += 256) {
        const int n = idx / 144, f = idx - n*144;
        int off;
        if (f < 16)      { off = f; }
        else if (f < 64) { int g = f-16; int u = g/3; off = 16 + (g-3*u)*16 + u; }
        else             { int g = f-64; int u = g/5; off = 64 + (g-5*u)*16 + u; }
        xT[n*148 + off] = feats[(size_t)nbase*144 + idx];
    }
    for (int idx = tid; idx < 724; idx += 256) cfS[idx] = fp.cf[idx];
    __syncthreads();

    const int h  = tid >> 7;
    const int nl = (tid >> 4) & 7;
    const int v  = tid & 15;
    const float* xb = xT + nl*148;
    float* cst = stage + (nl >> 1)*2592 + (nl & 1);

    if (h == 0) {
        do_cell<2,0,1,  2, 0, 0,  16, 0>(xb, wsT, cfS, cst, v);   // c02
        do_cell<1,2,2, 11,13, 0, 344, 4>(xb, wsT, cfS, cst, v);   // c21
        do_cell<2,2,3,  9,12,14, 472, 4>(xb, wsT, cfS, cst, v);   // c22
    } else {
        do_cell<0,0,1,  0, 0, 0,   0, 0>(xb, wsT, cfS, cst, v);   // c00
        do_cell<1,0,1,  1, 0, 0,   4, 0>(xb, wsT, cfS, cst, v);   // c01
        do_cell<0,1,1,  4, 0, 0,  56, 1>(xb, wsT, cfS, cst, v);   // c10
        do_cell<1,1,3,  3, 5, 7,  68, 1>(xb, wsT, cfS, cst, v);   // c11
        do_cell<2,1,2,  6, 8, 0, 176, 1>(xb, wsT, cfS, cst, v);   // c12
        do_cell<0,2,1, 10, 0, 0, 304, 4>(xb, wsT, cfS, cst, v);   // c20
    }
    __syncthreads();

    // coalesced copy stage -> g_C (4 np x 648 float4)
    {
        const int npbase = blockIdx.x * 4;
        for (int idx = tid; idx < 4*648; idx += 256) {
            const int np = idx / 648, q = idx - np*648;
            ((float4*)(g_C + (size_t)(npbase+np)*CROW))[q] =
                ((const float4*)(stage + np*2592))[q];
        }
    }
}

// ==================================================================
// K3: pair stage, K-THIRDS split for occupancy.
// Block = (cfg, rowhalf rg 0..1, kthird kt 0..2): grid 384, 512 thr.
// thread = (rp = tid>>5 node-pair, cg = tid&31); cols {cg, cg+32}.
// smem: Xs[64*148] + Cs[16 np * 864] = 23296 fl = 93184 B -> 2 blocks/SM.
// ==================================================================
#define XSTRIDE3 148
#define CTHIRD   864
#define SMEM_K3 ((64*XSTRIDE3 + 16*CTHIRD) * 4)

__global__ __launch_bounds__(512, 2) void k3_pairs(const float* __restrict__ feats)
{
    extern __shared__ float sm[];
    float* Xs = sm;                      // [64][148]
    float* Cs = sm + 64*XSTRIDE3;        // [16 np][864]
    const int tid = threadIdx.x;
    const int b   = blockIdx.x;
    const int cfg = b / 6;
    const int rem = b - cfg*6;
    const int rg  = rem / 3;
    const int kt  = rem - rg*3;

    {
        const float4* src = (const float4*)(feats + (size_t)cfg*9216);
        for (int idx = tid; idx < 2304; idx += 512) {
            const int col = idx / 36, q = idx - col*36;
            *(float4*)(Xs + col*XSTRIDE3 + q*4) = src[idx];
        }
    }
    {
        const int npbase = cfg*32 + rg*16;
        for (int idx = tid; idx < 16*216; idx += 512) {
            const int np = idx / 216, q = idx - np*216;
            ((float4*)(Cs + np*CTHIRD))[q] =
                ((const float4*)(g_C + (size_t)(npbase+np)*CROW + kt*CTHIRD))[q];
        }
    }
    __syncthreads();

    const int rp = tid >> 5;
    const int cg = tid & 31;
    const float* Crow = Cs + rp*CTHIRD;

    u64t acc[2][3];
    #pragma unroll
    for (int c = 0; c < 2; c++)
        #pragma unroll
        for (int k = 0; k < 3; k++) acc[c][k] = 0ULL;

    #pragma unroll 2
    for (int q = 0; q < 36; q++) {
        const float4 xv0 = *(const float4*)(Xs + cg*XSTRIDE3 + q*4);
        const float4 xv1 = *(const float4*)(Xs + (cg+32)*XSTRIDE3 + q*4);
        u64t xp0[4], xp1[4];
        xp0[0] = pk2(xv0.x, xv0.x); xp0[1] = pk2(xv0.y, xv0.y);
        xp0[2] = pk2(xv0.z, xv0.z); xp0[3] = pk2(xv0.w, xv0.w);
        xp1[0] = pk2(xv1.x, xv1.x); xp1[1] = pk2(xv1.y, xv1.y);
        xp1[2] = pk2(xv1.z, xv1.z); xp1[3] = pk2(xv1.w, xv1.w);
        #pragma unroll
        for (int k = 0; k < 3; k++) {
            const double2* cp = (const double2*)(Crow + (k*144 + q*4)*2);
            const double2 d0 = cp[0], d1 = cp[1];
            const u64t c0 = __double_as_longlong(d0.x);
            const u64t c1 = __double_as_longlong(d0.y);
            const u64t c2 = __double_as_longlong(d1.x);
            const u64t c3 = __double_as_longlong(d1.y);
            fma2(acc[0][k], c0, xp0[0]); fma2(acc[0][k], c1, xp0[1]);
            fma2(acc[0][k], c2, xp0[2]); fma2(acc[0][k], c3, xp0[3]);
            fma2(acc[1][k], c0, xp1[0]); fma2(acc[1][k], c1, xp1[1]);
            fma2(acc[1][k], c2, xp1[2]); fma2(acc[1][k], c3, xp1[3]);
        }
    }

    const int row0 = rg*32 + 2*rp;
    const int e0 = cfg*4096 + row0*64 + cg;
    #pragma unroll
    for (int c = 0; c < 2; c++) {
        const int ec = e0 + c*32;
        #pragma unroll
        for (int k = 0; k < 3; k++) {
            const int kg = kt*3 + k;
            float lo, hi; upk2(lo, hi, acc[c][k]);
            g_irr[(size_t)kg*NPAIRS + ec]      = lo;
            g_irr[(size_t)kg*NPAIRS + ec + 64] = hi;
        }
    }
}

// ==================================================================
// K4: cartesian change of basis + symmetrize; smem transpose tiles.
// Block = (cfg, 2x2 quadrant of 32x32 pairs): grid 256, 256 threads.
// ==================================================================
#define K4_A    0
#define K4_B    9216
#define K4_O    (9216 + 9504)
#define SMEM_K4 ((9216 + 9504 + 2304) * 4)

__global__ __launch_bounds__(256) void k4_cart(float* __restrict__ out, QParams qp)
{
    extern __shared__ float sm4[];
    float* A = sm4 + K4_A;
    float* B = sm4 + K4_B;
    float* obuf = sm4 + K4_O;
    const int tid = threadIdx.x;
    const int cfg = blockIdx.x >> 2;
    const int ib  = (blockIdx.x >> 1) & 1;
    const int jb  = blockIdx.x & 1;
    const int ebase = cfg*4096;

    for (int idx = tid; idx < 9216; idx += 256) {
        const int k = idx >> 10, p = idx & 1023, r = p >> 5, c = p & 31;
        A[idx] = g_irr[(size_t)k*NPAIRS + ebase + (ib*32+r)*64 + jb*32 + c];
        B[k*1056 + r*33 + c] =
            g_irr[(size_t)k*NPAIRS + ebase + (jb*32+r)*64 + ib*32 + c];
    }
    __syncthreads();

    for (int s = 0; s < 4; s++) {
        const int p = s*256 + tid;
        const int r = p >> 5, c = p & 31;
        float a[9], ap[9];
        #pragma unroll
        for (int k = 0; k < 9; k++) {
            a[k]  = A[k*1024 + p];
            ap[k] = B[k*1056 + c*33 + r];
        }
        #pragma unroll
        for (int ii = 0; ii < 3; ii++)
            #pragma unroll
            for (int jj = 0; jj < 3; jj++) {
                float sacc = 0.f;
                #pragma unroll
                for (int k = 0; k < 9; k++)
                    sacc += a[k]*qp.q[k*9 + ii*3 + jj] + ap[k]*qp.q[k*9 + jj*3 + ii];
                obuf[tid*9 + ii*3 + jj] = 0.5f * sacc;
            }
        __syncthreads();
        for (int idx = tid; idx < 576; idx += 256) {
            const int rl = idx / 72, q = idx - rl*72;
            ((float4*)(out + (size_t)(ebase + (ib*32 + s*8 + rl)*64 + jb*32)*9))[q] =
                ((const float4*)(obuf + rl*288))[q];
        }
        __syncthreads();
    }
}

// ==================================================================
// Host: real Wigner-3j (e3nn convention) + QCART + fold tables, per call.
// ==================================================================
static double h_fact(int n){ double r=1; for(int i=2;i<=n;i++) r*=i; return r; }

static double h_su2_cg(int j1,int m1,int j2,int m2,int j3,int m3){
    if (m3 != m1+m2) return 0.0;
    int vmin = std::max(std::max(-j1+j2+m3, -j1+m1), 0);
    int vmax = std::min(std::min(j2+j3+m1, j3-j1+j2), j3+m3);
    double C = sqrt((2.0*j3+1)*h_fact(j3+j1-j2)*h_fact(j3-j1+j2)*h_fact(j1+j2-j3)
               *h_fact(j3+m3)*h_fact(j3-m3)
               /(h_fact(j1+j2+j3+1)*h_fact(j1-m1)*h_fact(j1+m1)*h_fact(j2-m2)*h_fact(j2+m2)));
    double S = 0.0;
    for (int v = vmin; v <= vmax; v++) {
        double term = h_fact(j2+j3+m1-v)*h_fact(j1-m1+v)
                    /(h_fact(v)*h_fact(j3-j1+j2-v)*h_fact(j3+m3-v)*h_fact(v+j1-j2-m3));
        S += (((v+j2+m2) & 1) ? -1.0 : 1.0) * term;
    }
    return C*S;
}

typedef std::complex<double> cd;

static void h_qmat(int l, cd Q[5][5]){
    for (int i = 0; i < 5; i++) for (int j = 0; j < 5; j++) Q[i][j] = cd(0,0);
    const double s = 1.0/sqrt(2.0);
    for (int m = -l; m < 0; m++) {
        Q[l+m][l-m] = cd(s,0);
        Q[l+m][l+m] = cd(0,-s);
    }
    Q[l][l] = cd(1,0);
    for (int m = 1; m <= l; m++) {
        double sg = (m & 1) ? -1.0 : 1.0;
        Q[l+m][l+m] = cd(sg*s, 0);
        Q[l+m][l-m] = cd(0, sg*s);
    }
    cd f = (l==0) ? cd(1,0) : (l==1) ? cd(0,-1) : cd(-1,0);
    for (int i = 0; i < 5; i++) for (int j = 0; j < 5; j++) Q[i][j] *= f;
}

static void h_wigner3j(int l1,int l2,int l3, double W[5][5][5]){
    int d1 = 2*l1+1, d2 = 2*l2+1, d3 = 2*l3+1;
    double C[5][5][5] = {};
    for (int m1 = -l1; m1 <= l1; m1++)
        for (int m2 = -l2; m2 <= l2; m2++) {
            int m3 = m1+m2;
            if (m3 >= -l3 && m3 <= l3)
                C[l1+m1][l2+m2][l3+m3] = h_su2_cg(l1,m1,l2,m2,l3,m3);
        }
    cd Q1[5][5], Q2[5][5], Q3[5][5];
    h_qmat(l1,Q1); h_qmat(l2,Q2); h_qmat(l3,Q3);
    double nrm2 = 0.0;
    for (int j = 0; j < d1; j++)
      for (int lq = 0; lq < d2; lq++)
        for (int n = 0; n < d3; n++) {
            cd acc(0,0);
            for (int i = 0; i < d1; i++)
              for (int k = 0; k < d2; k++)
                for (int m = 0; m < d3; m++) {
                    double c = C[i][k][m];
                    if (c != 0.0) acc += Q1[i][j]*Q2[k][lq]*std::conj(Q3[m][n])*c;
                }
            W[j][lq][n] = acc.real();
            nrm2 += acc.real()*acc.real();
        }
    double inv = 1.0/sqrt(nrm2);
    for (int j = 0; j < d1; j++)
      for (int lq = 0; lq < d2; lq++)
        for (int n = 0; n < d3; n++) W[j][lq][n] *= inv;
}

static const int H_PL[15][3] = {{0,0,0},{1,1,0},{2,2,0},{0,1,1},{1,0,1},{1,1,1},
                                {1,2,1},{2,1,1},{2,2,1},{0,2,2},{2,0,2},{1,1,2},
                                {1,2,2},{2,1,2},{2,2,2}};
static const int H_W3OFF[15] = {0,1,10,35,44,53,80,125,170,245,270,295,340,415,490};

static void h_build_params(QParams& qp, FoldParams& fp){
    float w3[615];
    const double alpha[3] = { sqrt(1.0/768.0), sqrt(3.0/1536.0), sqrt(5.0/1536.0) };
    for (int p = 0; p < 15; p++) {
        int l1 = H_PL[p][0], l2 = H_PL[p][1], lo = H_PL[p][2];
        double W[5][5][5];
        h_wigner3j(l1,l2,lo,W);
        int jd = 2*l2+1, kd = 2*lo+1;
        for (int i = 0; i < 2*l1+1; i++)
          for (int j = 0; j < jd; j++)
            for (int k = 0; k < kd; k++)
                w3[H_W3OFF[p] + (i*jd+j)*kd + k] = (float)(alpha[lo]*W[i][j][k]);
    }
    int ko = 0;
    for (int l = 0; l <= 2; l++) {
        double W[5][5][5];
        h_wigner3j(1,1,l,W);
        double s = sqrt(2.0*l+1.0);
        for (int m = 0; m < 2*l+1; m++)
          for (int i = 0; i < 3; i++)
            for (int j = 0; j < 3; j++)
                qp.q[(ko+m)*9 + i*3 + j] = (float)(s*W[i][j][m]);
        ko += 2*l+1;
    }
    // cell-ordered fold coefficients, slices padded to multiples of 4.
    // cell order: lo-major (lo,l2) = (0,0)(0,1)(0,2)(1,0)(1,1)(1,2)(2,0)(2,1)(2,2)
    int nt = 0;
    for (int lo = 0; lo < 3; lo++) {
        const int kd = 2*lo+1;
        for (int l2 = 0; l2 < 3; l2++) {
            const int jd = 2*l2+1;
            const int S = (jd*kd + 3) & ~3;
            for (int p = 0; p < 15; p++) {
                if (H_PL[p][1] != l2 || H_PL[p][2] != lo) continue;
                for (int i = 0; i < 2*H_PL[p][0]+1; i++) {
                    for (int lin = 0; lin < S; lin++) {
                        if (lin < jd*kd) {
                            const int j = lin / kd, k = lin % kd;
                            fp.cf[nt++] = w3[H_W3OFF[p] + (i*jd + j)*kd + k];
                        } else fp.cf[nt++] = 0.0f;
                    }
                }
            }
        }
    }
    // nt == 724
}

// ==================================================================
extern "C" void kernel_launch(void* const* d_in, const int* in_sizes, int n_in,
                              void* d_out, int out_size)
{
    const float* feats = nullptr;
    const float* tpw   = nullptr;
    for (int i = 0; i < n_in; i++) {
        if (in_sizes[i] == NNODES*144)   feats = (const float*)d_in[i];
        else if (in_sizes[i] == 15*256)  tpw   = (const float*)d_in[i];
    }
    QParams qp; FoldParams fp;
    h_build_params(qp, fp);

    cudaFuncSetAttribute(k1_buildC, cudaFuncAttributeMaxDynamicSharedMemorySize, SMEM_K1);
    cudaFuncSetAttribute(k3_pairs,  cudaFuncAttributeMaxDynamicSharedMemorySize, SMEM_K3);
    cudaFuncSetAttribute(k4_cart,   cudaFuncAttributeMaxDynamicSharedMemorySize, SMEM_K4);

    k1_buildC<<<NNODES/8, 256, SMEM_K1>>>(feats, tpw, fp);
    k3_pairs<<<NCFG*6, 512, SMEM_K3>>>(feats);
    k4_cart<<<NCFG*4, 256, SMEM_K4>>>((float*)d_out, qp);
}

// round 13
// speedup vs baseline: 1.1593x; 1.1593x over previous
#include <cuda_runtime.h>
#include <cuda_bf16.h>
#include <math.h>
#include <complex>
#include <algorithm>

// ---------------- static problem shape ----------------
#define MUL    16
#define NCFG   64
#define NATOM  64
#define NNODES 4096
#define NPAIRS 262144
#define CROW   2600   // padded floats per node-pair row of g_C

// ---------------- device scratch (no allocation allowed) ----------------
// Row-pair-interleaved C: g_C[np*CROW + (kg*144 + b2)*2 + par]
__device__ float g_C[(size_t)2048 * CROW];
// planar irr: g_irr[k*NPAIRS + e]
__device__ float g_irr[(size_t)9 * NPAIRS];

struct QParams  { float q[81];  };   // QCART[k][3][3]
struct FoldParams { float cf[724]; };// cell-ordered fold coefficients (slices padded to 4)

// ---------------- f32x2 packed-math helpers ----------------
typedef unsigned long long u64t;
__device__ __forceinline__ u64t pk2(float lo, float hi){
    u64t r; asm("mov.b64 %0, {%1,%2};" : "=l"(r) : "f"(lo), "f"(hi)); return r;
}
__device__ __forceinline__ void fma2(u64t &d, u64t a, u64t b){
    asm("fma.rn.f32x2 %0, %1, %2, %0;" : "+l"(d) : "l"(a), "l"(b));
}
__device__ __forceinline__ void upk2(float &lo, float &hi, u64t v){
    asm("mov.b64 {%0,%1}, %2;" : "=f"(lo), "=f"(hi) : "l"(v));
}

// ==================================================================
// K1: per-node-PAIR C build, everything f32x2-packed.
// 256 blocks x 128 threads, 16 nodes (8 node-pairs)/block.
// thread = (np = tid>>4 in 0..7, v = tid&15): handles nodes 2np, 2np+1.
// smem regions (float offsets; all 16B-aligned):
//   cfP  u64[724]           @0      (5792 B)  (cf,cf) pairs
//   wsP  u64[15*16*18]      @1448   (34560 B) [p][v*18+u] = (w,w), padded
//   xP   u64[8*144]         @10088  (9216 B)  [np][off] = (x_n0, x_n1)
//   stage u64[8*720]        @12392  (46080 B) two-phase chunk buffer
// total 95648 B -> 2 blocks/SM (8 warps/SM).
// ==================================================================
#define K1_CF    0
#define K1_WS    1448
#define K1_XP    10088
#define K1_STAGE 12392
#define SMEM_K1  ((12392 + 11520) * 4)   // 95648 B

// one (lo,l2) cell for a node pair: accumulate out2[jd*kd] (f32x2),
// then STS.64 into the stage chunk. PHW = stage u64-width per np chunk.
template<int L2, int LO, int NP, int P0, int P1, int P2, int CFB, int CKG0, int PHW>
__device__ __forceinline__ void do_cell2(const u64t* __restrict__ xb,
                                         const u64t* __restrict__ wsP,
                                         const u64t* __restrict__ cfP,
                                         u64t* __restrict__ cst,
                                         const int v)
{
    constexpr int jd = 2*L2+1, kd = 2*LO+1;
    constexpr int S  = (jd*kd + 3) & ~3;
    constexpr int PLL[3] = {P0, P1, P2};
    constexpr int PD [15] = {1,3,5,1,3,3,3,5,5,1,5,3,3,5,5};
    constexpr int PFB[15] = {0,16,64,0,16,16,16,64,64,0,64,16,16,64,64};
    constexpr int L2B[3] = {0,16,64};

    u64t out2[jd*kd];
    #pragma unroll
    for (int q = 0; q < jd*kd; q++) out2[q] = 0ULL;

    int slice = 0;
    #pragma unroll
    for (int pp = 0; pp < NP; pp++) {
        const int p = PLL[pp];
        // cache (w,w) pairs for this (p, v): 16 u64 = 8 LDS.128
        const ulonglong2* w2p = (const ulonglong2*)(wsP + p*288 + v*18);
        u64t w2[16];
        #pragma unroll
        for (int g = 0; g < 8; g++) {
            const ulonglong2 t = w2p[g];
            w2[2*g] = t.x; w2[2*g+1] = t.y;
        }
        #pragma unroll
        for (int i = 0; i < PD[PLL[pp]]; i++) {
            const ulonglong2* x2p = (const ulonglong2*)(xb + PFB[PLL[pp]] + i*16);
            u64t t2 = 0ULL;
            #pragma unroll
            for (int g = 0; g < 8; g++) {
                const ulonglong2 xx = x2p[g];
                fma2(t2, w2[2*g], xx.x);
                fma2(t2, w2[2*g+1], xx.y);
            }
            const int co = CFB + slice*S;   // u64 index into cfP (even, 16B-aligned)
            #pragma unroll
            for (int g = 0; g < S/4; g++) {
                const ulonglong2 c01 = *(const ulonglong2*)(cfP + co + g*4);
                const ulonglong2 c23 = *(const ulonglong2*)(cfP + co + g*4 + 2);
                const u64t cc[4] = {c01.x, c01.y, c23.x, c23.y};
                #pragma unroll
                for (int l = 0; l < 4; l++) {
                    constexpr int JK = jd*kd;
                    const int lin = g*4 + l;
                    if (lin < JK) fma2(out2[lin], cc[l], t2);
                }
            }
            slice++;
        }
    }
    #pragma unroll
    for (int j = 0; j < jd; j++)
        #pragma unroll
        for (int k = 0; k < kd; k++)
            cst[(CKG0 + k)*144 + L2B[L2] + v*jd + j] = out2[j*kd + k];
    (void)PHW;
}

__global__ __launch_bounds__(128, 2) void k1_buildC(const float* __restrict__ feats,
                                                    const float* __restrict__ tpw,
                                                    FoldParams fp)
{
    extern __shared__ float sm1[];
    u64t* cfP   = (u64t*)(sm1 + K1_CF);
    u64t* wsP   = (u64t*)(sm1 + K1_WS);
    u64t* xP    = (u64t*)(sm1 + K1_XP);
    u64t* stage = (u64t*)(sm1 + K1_STAGE);
    const int tid = threadIdx.x;
    const int nbase = blockIdx.x * 16;        // 16 nodes per block

    // wsP: tpw[p*256 + u*16 + v] -> wsP[p*288 + v*18 + u] = (w,w)
    for (int idx = tid; idx < 3840; idx += 128) {
        const int p = idx >> 8, r = idx & 255, u = r >> 4, vv = r & 15;
        const float w = tpw[idx];
        wsP[p*288 + vv*18 + u] = pk2(w, w);
    }
    // xP: transposed feats pairs for 8 node-pairs
    for (int idx = tid; idx < 8*144; idx += 128) {
        const int np = idx / 144, f = idx - np*144;
        int off;
        if (f < 16)      { off = f; }
        else if (f < 64) { int g = f-16; int u = g/3; off = 16 + (g-3*u)*16 + u; }
        else             { int g = f-64; int u = g/5; off = 64 + (g-5*u)*16 + u; }
        const float x0 = feats[(size_t)(nbase + 2*np)*144 + f];
        const float x1 = feats[(size_t)(nbase + 2*np + 1)*144 + f];
        xP[np*144 + off] = pk2(x0, x1);
    }
    // cfP: duplicated pairs
    for (int idx = tid; idx < 724; idx += 128) {
        const float c = fp.cf[idx];
        cfP[idx] = pk2(c, c);
    }
    __syncthreads();

    const int np = tid >> 4;
    const int v  = tid & 15;
    const u64t* xb = xP + np*144;
    const int npg = blockIdx.x * 8;           // global node-pair base

    // ---- phase A: kg 0-3 (lo 0,1) -> stage chunk 576 u64/np ----
    {
        u64t* cst = stage + np*576;
        do_cell2<0,0,1,  0, 0, 0,   0, 0, 576>(xb, wsP, cfP, cst, v);   // c00
        do_cell2<1,0,1,  1, 0, 0,   4, 0, 576>(xb, wsP, cfP, cst, v);   // c01
        do_cell2<2,0,1,  2, 0, 0,  16, 0, 576>(xb, wsP, cfP, cst, v);   // c02
        do_cell2<0,1,1,  4, 0, 0,  56, 1, 576>(xb, wsP, cfP, cst, v);   // c10
        do_cell2<1,1,3,  3, 5, 7,  68, 1, 576>(xb, wsP, cfP, cst, v);   // c11
        do_cell2<2,1,2,  6, 8, 0, 176, 1, 576>(xb, wsP, cfP, cst, v);   // c12
    }
    __syncthreads();
    for (int idx = tid; idx < 8*288; idx += 128) {     // 288 float4 per np
        const int p = idx / 288, q = idx - p*288;
        ((float4*)(g_C + (size_t)(npg+p)*CROW))[q] =
            ((const float4*)(stage + p*576))[q];
    }
    __syncthreads();

    // ---- phase B: kg 4-8 (lo 2) -> stage chunk 720 u64/np ----
    {
        u64t* cst = stage + np*720;
        do_cell2<0,2,1, 10, 0, 0, 304, 0, 720>(xb, wsP, cfP, cst, v);   // c20
        do_cell2<1,2,2, 11,13, 0, 344, 0, 720>(xb, wsP, cfP, cst, v);   // c21
        do_cell2<2,2,3,  9,12,14, 472, 0, 720>(xb, wsP, cfP, cst, v);   // c22
    }
    __syncthreads();
    for (int idx = tid; idx < 8*360; idx += 128) {     // 360 float4 per np
        const int p = idx / 360, q = idx - p*360;
        ((float4*)(g_C + (size_t)(npg+p)*CROW + 1152))[q] =
            ((const float4*)(stage + p*720))[q];
    }
}

// ==================================================================
// K3: pair stage, 512 threads, warp-uniform C row (broadcast LDS).
// Block = (cfg, rowhalf of 32): grid 128.  (R9-exact)
// ==================================================================
#define XSTRIDE3 148
#define SMEM_K3 ((64*XSTRIDE3 + 16*CROW) * 4)

__global__ __launch_bounds__(512) void k3_pairs(const float* __restrict__ feats)
{
    extern __shared__ float sm[];
    float* Xs = sm;                      // [64][148]
    float* Cs = sm + 64*XSTRIDE3;        // [16 np][2600]
    const int tid = threadIdx.x;
    const int cfg = blockIdx.x >> 1;
    const int rg  = blockIdx.x & 1;

    {
        const float4* src = (const float4*)(feats + (size_t)cfg*9216);
        for (int idx = tid; idx < 2304; idx += 512) {
            const int col = idx / 36, q = idx - col*36;
            *(float4*)(Xs + col*XSTRIDE3 + q*4) = src[idx];
        }
    }
    {
        const int npbase = cfg*32 + rg*16;
        for (int idx = tid; idx < 16*648; idx += 512) {
            const int np = idx / 648, q = idx - np*648;
            ((float4*)(Cs + np*CROW))[q] =
                ((const float4*)(g_C + (size_t)(npbase+np)*CROW))[q];
        }
    }
    __syncthreads();

    const int rp = tid >> 5;
    const int cg = tid & 31;
    const float* Crow = Cs + rp*CROW;

    u64t acc[2][9];
    #pragma unroll
    for (int c = 0; c < 2; c++)
        #pragma unroll
        for (int k = 0; k < 9; k++) acc[c][k] = 0ULL;

    #pragma unroll 2
    for (int q = 0; q < 36; q++) {
        const float4 xv0 = *(const float4*)(Xs + cg*XSTRIDE3 + q*4);
        const float4 xv1 = *(const float4*)(Xs + (cg+32)*XSTRIDE3 + q*4);
        u64t xp0[4], xp1[4];
        xp0[0] = pk2(xv0.x, xv0.x); xp0[1] = pk2(xv0.y, xv0.y);
        xp0[2] = pk2(xv0.z, xv0.z); xp0[3] = pk2(xv0.w, xv0.w);
        xp1[0] = pk2(xv1.x, xv1.x); xp1[1] = pk2(xv1.y, xv1.y);
        xp1[2] = pk2(xv1.z, xv1.z); xp1[3] = pk2(xv1.w, xv1.w);
        #pragma unroll
        for (int k = 0; k < 9; k++) {
            const double2* cp = (const double2*)(Crow + (k*144 + q*4)*2);
            const double2 d0 = cp[0], d1 = cp[1];
            const u64t c0 = __double_as_longlong(d0.x);
            const u64t c1 = __double_as_longlong(d0.y);
            const u64t c2 = __double_as_longlong(d1.x);
            const u64t c3 = __double_as_longlong(d1.y);
            fma2(acc[0][k], c0, xp0[0]); fma2(acc[0][k], c1, xp0[1]);
            fma2(acc[0][k], c2, xp0[2]); fma2(acc[0][k], c3, xp0[3]);
            fma2(acc[1][k], c0, xp1[0]); fma2(acc[1][k], c1, xp1[1]);
            fma2(acc[1][k], c2, xp1[2]); fma2(acc[1][k], c3, xp1[3]);
        }
    }

    const int row0 = rg*32 + 2*rp;
    const int e0 = cfg*4096 + row0*64 + cg;
    #pragma unroll
    for (int c = 0; c < 2; c++) {
        const int ec = e0 + c*32;
        #pragma unroll
        for (int k = 0; k < 9; k++) {
            float lo, hi; upk2(lo, hi, acc[c][k]);
            g_irr[(size_t)k*NPAIRS + ec]      = lo;
            g_irr[(size_t)k*NPAIRS + ec + 64] = hi;
        }
    }
}

// ==================================================================
// K4: cartesian change of basis + symmetrize; smem transpose tiles.
// Block = (cfg, 2x2 quadrant of 32x32 pairs): grid 256, 256 threads. (R9-exact)
// ==================================================================
#define K4_A    0
#define K4_B    9216
#define K4_O    (9216 + 9504)
#define SMEM_K4 ((9216 + 9504 + 2304) * 4)

__global__ __launch_bounds__(256) void k4_cart(float* __restrict__ out, QParams qp)
{
    extern __shared__ float sm4[];
    float* A = sm4 + K4_A;
    float* B = sm4 + K4_B;
    float* obuf = sm4 + K4_O;
    const int tid = threadIdx.x;
    const int cfg = blockIdx.x >> 2;
    const int ib  = (blockIdx.x >> 1) & 1;
    const int jb  = blockIdx.x & 1;
    const int ebase = cfg*4096;

    for (int idx = tid; idx < 9216; idx += 256) {
        const int k = idx >> 10, p = idx & 1023, r = p >> 5, c = p & 31;
        A[idx] = g_irr[(size_t)k*NPAIRS + ebase + (ib*32+r)*64 + jb*32 + c];
        B[k*1056 + r*33 + c] =
            g_irr[(size_t)k*NPAIRS + ebase + (jb*32+r)*64 + ib*32 + c];
    }
    __syncthreads();

    for (int s = 0; s < 4; s++) {
        const int p = s*256 + tid;
        const int r = p >> 5, c = p & 31;
        float a[9], ap[9];
        #pragma unroll
        for (int k = 0; k < 9; k++) {
            a[k]  = A[k*1024 + p];
            ap[k] = B[k*1056 + c*33 + r];
        }
        #pragma unroll
        for (int ii = 0; ii < 3; ii++)
            #pragma unroll
            for (int jj = 0; jj < 3; jj++) {
                float sacc = 0.f;
                #pragma unroll
                for (int k = 0; k < 9; k++)
                    sacc += a[k]*qp.q[k*9 + ii*3 + jj] + ap[k]*qp.q[k*9 + jj*3 + ii];
                obuf[tid*9 + ii*3 + jj] = 0.5f * sacc;
            }
        __syncthreads();
        for (int idx = tid; idx < 576; idx += 256) {
            const int rl = idx / 72, q = idx - rl*72;
            ((float4*)(out + (size_t)(ebase + (ib*32 + s*8 + rl)*64 + jb*32)*9))[q] =
                ((const float4*)(obuf + rl*288))[q];
        }
        __syncthreads();
    }
}

// ==================================================================
// Host: real Wigner-3j (e3nn convention) + QCART + fold tables, per call.
// ==================================================================
static double h_fact(int n){ double r=1; for(int i=2;i<=n;i++) r*=i; return r; }

static double h_su2_cg(int j1,int m1,int j2,int m2,int j3,int m3){
    if (m3 != m1+m2) return 0.0;
    int vmin = std::max(std::max(-j1+j2+m3, -j1+m1), 0);
    int vmax = std::min(std::min(j2+j3+m1, j3-j1+j2), j3+m3);
    double C = sqrt((2.0*j3+1)*h_fact(j3+j1-j2)*h_fact(j3-j1+j2)*h_fact(j1+j2-j3)
               *h_fact(j3+m3)*h_fact(j3-m3)
               /(h_fact(j1+j2+j3+1)*h_fact(j1-m1)*h_fact(j1+m1)*h_fact(j2-m2)*h_fact(j2+m2)));
    double S = 0.0;
    for (int v = vmin; v <= vmax; v++) {
        double term = h_fact(j2+j3+m1-v)*h_fact(j1-m1+v)
                    /(h_fact(v)*h_fact(j3-j1+j2-v)*h_fact(j3+m3-v)*h_fact(v+j1-j2-m3));
        S += (((v+j2+m2) & 1) ? -1.0 : 1.0) * term;
    }
    return C*S;
}

typedef std::complex<double> cd;

static void h_qmat(int l, cd Q[5][5]){
    for (int i = 0; i < 5; i++) for (int j = 0; j < 5; j++) Q[i][j] = cd(0,0);
    const double s = 1.0/sqrt(2.0);
    for (int m = -l; m < 0; m++) {
        Q[l+m][l-m] = cd(s,0);
        Q[l+m][l+m] = cd(0,-s);
    }
    Q[l][l] = cd(1,0);
    for (int m = 1; m <= l; m++) {
        double sg = (m & 1) ? -1.0 : 1.0;
        Q[l+m][l+m] = cd(sg*s, 0);
        Q[l+m][l-m] = cd(0, sg*s);
    }
    cd f = (l==0) ? cd(1,0) : (l==1) ? cd(0,-1) : cd(-1,0);
    for (int i = 0; i < 5; i++) for (int j = 0; j < 5; j++) Q[i][j] *= f;
}

static void h_wigner3j(int l1,int l2,int l3, double W[5][5][5]){
    int d1 = 2*l1+1, d2 = 2*l2+1, d3 = 2*l3+1;
    double C[5][5][5] = {};
    for (int m1 = -l1; m1 <= l1; m1++)
        for (int m2 = -l2; m2 <= l2; m2++) {
            int m3 = m1+m2;
            if (m3 >= -l3 && m3 <= l3)
                C[l1+m1][l2+m2][l3+m3] = h_su2_cg(l1,m1,l2,m2,l3,m3);
        }
    cd Q1[5][5], Q2[5][5], Q3[5][5];
    h_qmat(l1,Q1); h_qmat(l2,Q2); h_qmat(l3,Q3);
    double nrm2 = 0.0;
    for (int j = 0; j < d1; j++)
      for (int lq = 0; lq < d2; lq++)
        for (int n = 0; n < d3; n++) {
            cd acc(0,0);
            for (int i = 0; i < d1; i++)
              for (int k = 0; k < d2; k++)
                for (int m = 0; m < d3; m++) {
                    double c = C[i][k][m];
                    if (c != 0.0) acc += Q1[i][j]*Q2[k][lq]*std::conj(Q3[m][n])*c;
                }
            W[j][lq][n] = acc.real();
            nrm2 += acc.real()*acc.real();
        }
    double inv = 1.0/sqrt(nrm2);
    for (int j = 0; j < d1; j++)
      for (int lq = 0; lq < d2; lq++)
        for (int n = 0; n < d3; n++) W[j][lq][n] *= inv;
}

static const int H_PL[15][3] = {{0,0,0},{1,1,0},{2,2,0},{0,1,1},{1,0,1},{1,1,1},
                                {1,2,1},{2,1,1},{2,2,1},{0,2,2},{2,0,2},{1,1,2},
                                {1,2,2},{2,1,2},{2,2,2}};
static const int H_W3OFF[15] = {0,1,10,35,44,53,80,125,170,245,270,295,340,415,490};

static void h_build_params(QParams& qp, FoldParams& fp){
    float w3[615];
    const double alpha[3] = { sqrt(1.0/768.0), sqrt(3.0/1536.0), sqrt(5.0/1536.0) };
    for (int p = 0; p < 15; p++) {
        int l1 = H_PL[p][0], l2 = H_PL[p][1], lo = H_PL[p][2];
        double W[5][5][5];
        h_wigner3j(l1,l2,lo,W);
        int jd = 2*l2+1, kd = 2*lo+1;
        for (int i = 0; i < 2*l1+1; i++)
          for (int j = 0; j < jd; j++)
            for (int k = 0; k < kd; k++)
                w3[H_W3OFF[p] + (i*jd+j)*kd + k] = (float)(alpha[lo]*W[i][j][k]);
    }
    int ko = 0;
    for (int l = 0; l <= 2; l++) {
        double W[5][5][5];
        h_wigner3j(1,1,l,W);
        double s = sqrt(2.0*l+1.0);
        for (int m = 0; m < 2*l+1; m++)
          for (int i = 0; i < 3; i++)
            for (int j = 0; j < 3; j++)
                qp.q[(ko+m)*9 + i*3 + j] = (float)(s*W[i][j][m]);
        ko += 2*l+1;
    }
    // cell-ordered fold coefficients, slices padded to multiples of 4.
    // cell order: lo-major (lo,l2) = (0,0)(0,1)(0,2)(1,0)(1,1)(1,2)(2,0)(2,1)(2,2)
    int nt = 0;
    for (int lo = 0; lo < 3; lo++) {
        const int kd = 2*lo+1;
        for (int l2 = 0; l2 < 3; l2++) {
            const int jd = 2*l2+1;
            const int S = (jd*kd + 3) & ~3;
            for (int p = 0; p < 15; p++) {
                if (H_PL[p][1] != l2 || H_PL[p][2] != lo) continue;
                for (int i = 0; i < 2*H_PL[p][0]+1; i++) {
                    for (int lin = 0; lin < S; lin++) {
                        if (lin < jd*kd) {
                            const int j = lin / kd, k = lin % kd;
                            fp.cf[nt++] = w3[H_W3OFF[p] + (i*jd + j)*kd + k];
                        } else fp.cf[nt++] = 0.0f;
                    }
                }
            }
        }
    }
    // nt == 724
}

// ==================================================================
extern "C" void kernel_launch(void* const* d_in, const int* in_sizes, int n_in,
                              void* d_out, int out_size)
{
    const float* feats = nullptr;
    const float* tpw   = nullptr;
    for (int i = 0; i < n_in; i++) {
        if (in_sizes[i] == NNODES*144)   feats = (const float*)d_in[i];
        else if (in_sizes[i] == 15*256)  tpw   = (const float*)d_in[i];
    }
    QParams qp; FoldParams fp;
    h_build_params(qp, fp);

    cudaFuncSetAttribute(k1_buildC, cudaFuncAttributeMaxDynamicSharedMemorySize, SMEM_K1);
    cudaFuncSetAttribute(k3_pairs,  cudaFuncAttributeMaxDynamicSharedMemorySize, SMEM_K3);
    cudaFuncSetAttribute(k4_cart,   cudaFuncAttributeMaxDynamicSharedMemorySize, SMEM_K4);

    k1_buildC<<<NNODES/16, 128, SMEM_K1>>>(feats, tpw, fp);
    k3_pairs<<<NCFG*2, 512, SMEM_K3>>>(feats);
    k4_cart<<<NCFG*4, 256, SMEM_K4>>>((float*)d_out, qp);
}

// round 16
// speedup vs baseline: 1.2091x; 1.0430x over previous
#include <cuda_runtime.h>
#include <cuda_bf16.h>
#include <math.h>
#include <complex>
#include <algorithm>

// ---------------- static problem shape ----------------
#define MUL    16
#define NCFG   64
#define NATOM  64
#define NNODES 4096
#define NPAIRS 262144
#define CROW   2600   // padded floats per node-pair row of g_C

// ---------------- device scratch (no allocation allowed) ----------------
// Row-pair-interleaved C: g_C[np*CROW + (kg*144 + b2)*2 + par]
__device__ float g_C[(size_t)2048 * CROW];
// planar irr: g_irr[k*NPAIRS + e]
__device__ float g_irr[(size_t)9 * NPAIRS];

struct QParams  { float q[81];  };   // QCART[k][3][3]
struct FoldParams { float cf[724]; };// cell-ordered fold coefficients (slices padded to 4)

// ---------------- f32x2 packed-math helpers ----------------
typedef unsigned long long u64t;
__device__ __forceinline__ u64t pk2(float lo, float hi){
    u64t r; asm("mov.b64 %0, {%1,%2};" : "=l"(r) : "f"(lo), "f"(hi)); return r;
}
__device__ __forceinline__ void fma2(u64t &d, u64t a, u64t b){
    asm("fma.rn.f32x2 %0, %1, %2, %0;" : "+l"(d) : "l"(a), "l"(b));
}
__device__ __forceinline__ u64t add2(u64t a, u64t b){
    u64t r; asm("add.rn.f32x2 %0, %1, %2;" : "=l"(r) : "l"(a), "l"(b)); return r;
}
__device__ __forceinline__ void upk2(float &lo, float &hi, u64t v){
    asm("mov.b64 {%0,%1}, %2;" : "=f"(lo), "=f"(hi) : "l"(v));
}

// ==================================================================
// K1: per-node-PAIR C build, f32x2-packed, cell-split across threads.
// 512 blocks x 128 threads, 8 nodes (4 node-pairs)/block.
// thread = (h = tid>>6, np = (tid>>4)&3, v = tid&15).
// smem (floats): cf[724] @0 | wsT[4800] @724 | xP u64 @5524 (1152 fl)
//                | stage u64 @6676 (5760 fl)   total 12436 fl = 49744 B
// 4 blocks/SM capacity -> grid 512 resident in one wave (~14 warps/SM).
// ==================================================================
#define K1_CF    0
#define K1_WS    724
#define K1_XP    5524
#define K1_STAGE 6676
#define SMEM_K1  (12436 * 4)

// one (lo,l2) cell for a node pair: accumulate out2[jd*kd] (f32x2),
// then STS.64 into the stage chunk.
template<int L2, int LO, int NP, int P0, int P1, int P2, int CFB, int CKG0>
__device__ __forceinline__ void do_cell2(const u64t* __restrict__ xb,
                                         const float* __restrict__ wsT,
                                         const float* __restrict__ cfS,
                                         u64t* __restrict__ cst,
                                         const int v)
{
    constexpr int jd = 2*L2+1, kd = 2*LO+1;
    constexpr int S  = (jd*kd + 3) & ~3;
    constexpr int PLL[3] = {P0, P1, P2};
    constexpr int PD [15] = {1,3,5,1,3,3,3,5,5,1,5,3,3,5,5};
    constexpr int PFB[15] = {0,16,64,0,16,16,16,64,64,0,64,16,16,64,64};
    constexpr int L2B[3] = {0,16,64};

    u64t out2[jd*kd];
    #pragma unroll
    for (int q = 0; q < jd*kd; q++) out2[q] = 0ULL;

    int slice = 0;
    #pragma unroll
    for (int pp = 0; pp < NP; pp++) {
        const int p = PLL[pp];
        // load w (floats) and duplicate into f32x2 pairs
        const float4* w4 = (const float4*)(wsT + p*320 + v*20);
        const float4 wa = w4[0], wb = w4[1], wc = w4[2], wd = w4[3];
        u64t w2[16];
        w2[0]=pk2(wa.x,wa.x); w2[1]=pk2(wa.y,wa.y); w2[2]=pk2(wa.z,wa.z); w2[3]=pk2(wa.w,wa.w);
        w2[4]=pk2(wb.x,wb.x); w2[5]=pk2(wb.y,wb.y); w2[6]=pk2(wb.z,wb.z); w2[7]=pk2(wb.w,wb.w);
        w2[8]=pk2(wc.x,wc.x); w2[9]=pk2(wc.y,wc.y); w2[10]=pk2(wc.z,wc.z); w2[11]=pk2(wc.w,wc.w);
        w2[12]=pk2(wd.x,wd.x); w2[13]=pk2(wd.y,wd.y); w2[14]=pk2(wd.z,wd.z); w2[15]=pk2(wd.w,wd.w);
        #pragma unroll
        for (int i = 0; i < PD[PLL[pp]]; i++) {
            const ulonglong2* x2p = (const ulonglong2*)(xb + PFB[PLL[pp]] + i*16);
            // 4 independent partial chains, then 2-level combine
            u64t t0 = 0ULL, t1 = 0ULL, t2v = 0ULL, t3 = 0ULL;
            {
                const ulonglong2 x0 = x2p[0], x1 = x2p[1], x2 = x2p[2], x3 = x2p[3];
                fma2(t0, w2[0], x0.x);  fma2(t0, w2[1], x0.y);
                fma2(t1, w2[2], x1.x);  fma2(t1, w2[3], x1.y);
                fma2(t2v, w2[4], x2.x); fma2(t2v, w2[5], x2.y);
                fma2(t3, w2[6], x3.x);  fma2(t3, w2[7], x3.y);
            }
            {
                const ulonglong2 x4 = x2p[4], x5 = x2p[5], x6 = x2p[6], x7 = x2p[7];
                fma2(t0, w2[8], x4.x);  fma2(t0, w2[9], x4.y);
                fma2(t1, w2[10], x5.x); fma2(t1, w2[11], x5.y);
                fma2(t2v, w2[12], x6.x); fma2(t2v, w2[13], x6.y);
                fma2(t3, w2[14], x7.x); fma2(t3, w2[15], x7.y);
            }
            const u64t t = add2(add2(t0, t1), add2(t2v, t3));

            const int co = CFB + slice*S;
            #pragma unroll
            for (int g = 0; g < S/4; g++) {
                const float4 c4 = *(const float4*)(cfS + co + g*4);
                const float cc[4] = {c4.x, c4.y, c4.z, c4.w};
                #pragma unroll
                for (int l = 0; l < 4; l++) {
                    constexpr int JK = jd*kd;
                    const int lin = g*4 + l;
                    if (lin < JK) fma2(out2[lin], pk2(cc[l], cc[l]), t);
                }
            }
            slice++;
        }
    }
    #pragma unroll
    for (int j = 0; j < jd; j++)
        #pragma unroll
        for (int k = 0; k < kd; k++)
            cst[(CKG0 + k)*144 + L2B[L2] + v*jd + j] = out2[j*kd + k];
}

__global__ __launch_bounds__(128, 4) void k1_buildC(const float* __restrict__ feats,
                                                    const float* __restrict__ tpw,
                                                    FoldParams fp)
{
    extern __shared__ float sm1[];
    float* cfS   = sm1 + K1_CF;
    float* wsT   = sm1 + K1_WS;
    u64t*  xP    = (u64t*)(sm1 + K1_XP);
    u64t*  stage = (u64t*)(sm1 + K1_STAGE);
    const int tid = threadIdx.x;
    const int nbase = blockIdx.x * 8;         // 8 nodes per block
    const int npg   = blockIdx.x * 4;         // 4 node-pairs per block

    // wsT: tpw[p*256 + u*16 + v] -> wsT[p*320 + v*20 + u]
    for (int idx = tid; idx < 3840; idx += 128) {
        const int p = idx >> 8, r = idx & 255, u = r >> 4, vv = r & 15;
        wsT[p*320 + vv*20 + u] = tpw[idx];
    }
    // xP: transposed feats pairs for 4 node-pairs
    for (int idx = tid; idx < 4*144; idx += 128) {
        const int np = idx / 144, f = idx - np*144;
        int off;
        if (f < 16)      { off = f; }
        else if (f < 64) { int g = f-16; int u = g/3; off = 16 + (g-3*u)*16 + u; }
        else             { int g = f-64; int u = g/5; off = 64 + (g-5*u)*16 + u; }
        const float x0 = feats[(size_t)(nbase + 2*np)*144 + f];
        const float x1 = feats[(size_t)(nbase + 2*np + 1)*144 + f];
        xP[np*144 + off] = pk2(x0, x1);
    }
    for (int idx = tid; idx < 724; idx += 128) cfS[idx] = fp.cf[idx];
    __syncthreads();

    const int h  = tid >> 6;
    const int np = (tid >> 4) & 3;
    const int v  = tid & 15;
    const u64t* xb = xP + np*144;

    // ---- phase A: kg 0-3 (lo 0,1) -> stage chunk 576 u64/np ----
    {
        u64t* cst = stage + np*576;
        if (h == 0) {
            do_cell2<0,0,1,  0, 0, 0,   0, 0>(xb, wsT, cfS, cst, v);   // c00
            do_cell2<2,0,1,  2, 0, 0,  16, 0>(xb, wsT, cfS, cst, v);   // c02
            do_cell2<2,1,2,  6, 8, 0, 176, 1>(xb, wsT, cfS, cst, v);   // c12
        } else {
            do_cell2<1,0,1,  1, 0, 0,   4, 0>(xb, wsT, cfS, cst, v);   // c01
            do_cell2<0,1,1,  4, 0, 0,  56, 1>(xb, wsT, cfS, cst, v);   // c10
            do_cell2<1,1,3,  3, 5, 7,  68, 1>(xb, wsT, cfS, cst, v);   // c11
        }
    }
    __syncthreads();
    for (int idx = tid; idx < 4*288; idx += 128) {     // 288 float4 per np
        const int p = idx / 288, q = idx - p*288;
        ((float4*)(g_C + (size_t)(npg+p)*CROW))[q] =
            ((const float4*)(stage + p*576))[q];
    }
    __syncthreads();

    // ---- phase B: kg 4-8 (lo 2) -> stage chunk 720 u64/np ----
    {
        u64t* cst = stage + np*720;
        if (h == 0) {
            do_cell2<2,2,3,  9,12,14, 472, 0>(xb, wsT, cfS, cst, v);   // c22
        } else {
            do_cell2<0,2,1, 10, 0, 0, 304, 0>(xb, wsT, cfS, cst, v);   // c20
            do_cell2<1,2,2, 11,13, 0, 344, 0>(xb, wsT, cfS, cst, v);   // c21
        }
    }
    __syncthreads();
    for (int idx = tid; idx < 4*360; idx += 128) {     // 360 float4 per np
        const int p = idx / 360, q = idx - p*360;
        ((float4*)(g_C + (size_t)(npg+p)*CROW + 1152))[q] =
            ((const float4*)(stage + p*720))[q];
    }
}

// ==================================================================
// K3: pair stage, 512 threads, warp-uniform C row (broadcast LDS).
// Block = (cfg, rowhalf of 32): grid 128.  (R9-exact)
// ==================================================================
#define XSTRIDE3 148
#define SMEM_K3 ((64*XSTRIDE3 + 16*CROW) * 4)

__global__ __launch_bounds__(512) void k3_pairs(const float* __restrict__ feats)
{
    extern __shared__ float sm[];
    float* Xs = sm;                      // [64][148]
    float* Cs = sm + 64*XSTRIDE3;        // [16 np][2600]
    const int tid = threadIdx.x;
    const int cfg = blockIdx.x >> 1;
    const int rg  = blockIdx.x & 1;

    {
        const float4* src = (const float4*)(feats + (size_t)cfg*9216);
        for (int idx = tid; idx < 2304; idx += 512) {
            const int col = idx / 36, q = idx - col*36;
            *(float4*)(Xs + col*XSTRIDE3 + q*4) = src[idx];
        }
    }
    {
        const int npbase = cfg*32 + rg*16;
        for (int idx = tid; idx < 16*648; idx += 512) {
            const int np = idx / 648, q = idx - np*648;
            ((float4*)(Cs + np*CROW))[q] =
                ((const float4*)(g_C + (size_t)(npbase+np)*CROW))[q];
        }
    }
    __syncthreads();

    const int rp = tid >> 5;
    const int cg = tid & 31;
    const float* Crow = Cs + rp*CROW;

    u64t acc[2][9];
    #pragma unroll
    for (int c = 0; c < 2; c++)
        #pragma unroll
        for (int k = 0; k < 9; k++) acc[c][k] = 0ULL;

    #pragma unroll 2
    for (int q = 0; q < 36; q++) {
        const float4 xv0 = *(const float4*)(Xs + cg*XSTRIDE3 + q*4);
        const float4 xv1 = *(const float4*)(Xs + (cg+32)*XSTRIDE3 + q*4);
        u64t xp0[4], xp1[4];
        xp0[0] = pk2(xv0.x, xv0.x); xp0[1] = pk2(xv0.y, xv0.y);
        xp0[2] = pk2(xv0.z, xv0.z); xp0[3] = pk2(xv0.w, xv0.w);
        xp1[0] = pk2(xv1.x, xv1.x); xp1[1] = pk2(xv1.y, xv1.y);
        xp1[2] = pk2(xv1.z, xv1.z); xp1[3] = pk2(xv1.w, xv1.w);
        #pragma unroll
        for (int k = 0; k < 9; k++) {
            const double2* cp = (const double2*)(Crow + (k*144 + q*4)*2);
            const double2 d0 = cp[0], d1 = cp[1];
            const u64t c0 = __double_as_longlong(d0.x);
            const u64t c1 = __double_as_longlong(d0.y);
            const u64t c2 = __double_as_longlong(d1.x);
            const u64t c3 = __double_as_longlong(d1.y);
            fma2(acc[0][k], c0, xp0[0]); fma2(acc[0][k], c1, xp0[1]);
            fma2(acc[0][k], c2, xp0[2]); fma2(acc[0][k], c3, xp0[3]);
            fma2(acc[1][k], c0, xp1[0]); fma2(acc[1][k], c1, xp1[1]);
            fma2(acc[1][k], c2, xp1[2]); fma2(acc[1][k], c3, xp1[3]);
        }
    }

    const int row0 = rg*32 + 2*rp;
    const int e0 = cfg*4096 + row0*64 + cg;
    #pragma unroll
    for (int c = 0; c < 2; c++) {
        const int ec = e0 + c*32;
        #pragma unroll
        for (int k = 0; k < 9; k++) {
            float lo, hi; upk2(lo, hi, acc[c][k]);
            g_irr[(size_t)k*NPAIRS + ec]      = lo;
            g_irr[(size_t)k*NPAIRS + ec + 64] = hi;
        }
    }
}

// ==================================================================
// K4: cartesian change of basis + symmetrize; smem transpose tiles.
// Block = (cfg, 2x2 quadrant of 32x32 pairs): grid 256, 256 threads. (R9-exact)
// ==================================================================
#define K4_A    0
#define K4_B    9216
#define K4_O    (9216 + 9504)
#define SMEM_K4 ((9216 + 9504 + 2304) * 4)

__global__ __launch_bounds__(256) void k4_cart(float* __restrict__ out, QParams qp)
{
    extern __shared__ float sm4[];
    float* A = sm4 + K4_A;
    float* B = sm4 + K4_B;
    float* obuf = sm4 + K4_O;
    const int tid = threadIdx.x;
    const int cfg = blockIdx.x >> 2;
    const int ib  = (blockIdx.x >> 1) & 1;
    const int jb  = blockIdx.x & 1;
    const int ebase = cfg*4096;

    for (int idx = tid; idx < 9216; idx += 256) {
        const int k = idx >> 10, p = idx & 1023, r = p >> 5, c = p & 31;
        A[idx] = g_irr[(size_t)k*NPAIRS + ebase + (ib*32+r)*64 + jb*32 + c];
        B[k*1056 + r*33 + c] =
            g_irr[(size_t)k*NPAIRS + ebase + (jb*32+r)*64 + ib*32 + c];
    }
    __syncthreads();

    for (int s = 0; s < 4; s++) {
        const int p = s*256 + tid;
        const int r = p >> 5, c = p & 31;
        float a[9], ap[9];
        #pragma unroll
        for (int k = 0; k < 9; k++) {
            a[k]  = A[k*1024 + p];
            ap[k] = B[k*1056 + c*33 + r];
        }
        #pragma unroll
        for (int ii = 0; ii < 3; ii++)
            #pragma unroll
            for (int jj = 0; jj < 3; jj++) {
                float sacc = 0.f;
                #pragma unroll
                for (int k = 0; k < 9; k++)
                    sacc += a[k]*qp.q[k*9 + ii*3 + jj] + ap[k]*qp.q[k*9 + jj*3 + ii];
                obuf[tid*9 + ii*3 + jj] = 0.5f * sacc;
            }
        __syncthreads();
        for (int idx = tid; idx < 576; idx += 256) {
            const int rl = idx / 72, q = idx - rl*72;
            ((float4*)(out + (size_t)(ebase + (ib*32 + s*8 + rl)*64 + jb*32)*9))[q] =
                ((const float4*)(obuf + rl*288))[q];
        }
        __syncthreads();
    }
}

// ==================================================================
// Host: real Wigner-3j (e3nn convention) + QCART + fold tables, per call.
// ==================================================================
static double h_fact(int n){ double r=1; for(int i=2;i<=n;i++) r*=i; return r; }

static double h_su2_cg(int j1,int m1,int j2,int m2,int j3,int m3){
    if (m3 != m1+m2) return 0.0;
    int vmin = std::max(std::max(-j1+j2+m3, -j1+m1), 0);
    int vmax = std::min(std::min(j2+j3+m1, j3-j1+j2), j3+m3);
    double C = sqrt((2.0*j3+1)*h_fact(j3+j1-j2)*h_fact(j3-j1+j2)*h_fact(j1+j2-j3)
               *h_fact(j3+m3)*h_fact(j3-m3)
               /(h_fact(j1+j2+j3+1)*h_fact(j1-m1)*h_fact(j1+m1)*h_fact(j2-m2)*h_fact(j2+m2)));
    double S = 0.0;
    for (int v = vmin; v <= vmax; v++) {
        double term = h_fact(j2+j3+m1-v)*h_fact(j1-m1+v)
                    /(h_fact(v)*h_fact(j3-j1+j2-v)*h_fact(j3+m3-v)*h_fact(v+j1-j2-m3));
        S += (((v+j2+m2) & 1) ? -1.0 : 1.0) * term;
    }
    return C*S;
}

typedef std::complex<double> cd;

static void h_qmat(int l, cd Q[5][5]){
    for (int i = 0; i < 5; i++) for (int j = 0; j < 5; j++) Q[i][j] = cd(0,0);
    const double s = 1.0/sqrt(2.0);
    for (int m = -l; m < 0; m++) {
        Q[l+m][l-m] = cd(s,0);
        Q[l+m][l+m] = cd(0,-s);
    }
    Q[l][l] = cd(1,0);
    for (int m = 1; m <= l; m++) {
        double sg = (m & 1) ? -1.0 : 1.0;
        Q[l+m][l+m] = cd(sg*s, 0);
        Q[l+m][l-m] = cd(0, sg*s);
    }
    cd f = (l==0) ? cd(1,0) : (l==1) ? cd(0,-1) : cd(-1,0);
    for (int i = 0; i < 5; i++) for (int j = 0; j < 5; j++) Q[i][j] *= f;
}

static void h_wigner3j(int l1,int l2,int l3, double W[5][5][5]){
    int d1 = 2*l1+1, d2 = 2*l2+1, d3 = 2*l3+1;
    double C[5][5][5] = {};
    for (int m1 = -l1; m1 <= l1; m1++)
        for (int m2 = -l2; m2 <= l2; m2++) {
            int m3 = m1+m2;
            if (m3 >= -l3 && m3 <= l3)
                C[l1+m1][l2+m2][l3+m3] = h_su2_cg(l1,m1,l2,m2,l3,m3);
        }
    cd Q1[5][5], Q2[5][5], Q3[5][5];
    h_qmat(l1,Q1); h_qmat(l2,Q2); h_qmat(l3,Q3);
    double nrm2 = 0.0;
    for (int j = 0; j < d1; j++)
      for (int lq = 0; lq < d2; lq++)
        for (int n = 0; n < d3; n++) {
            cd acc(0,0);
            for (int i = 0; i < d1; i++)
              for (int k = 0; k < d2; k++)
                for (int m = 0; m < d3; m++) {
                    double c = C[i][k][m];
                    if (c != 0.0) acc += Q1[i][j]*Q2[k][lq]*std::conj(Q3[m][n])*c;
                }
            W[j][lq][n] = acc.real();
            nrm2 += acc.real()*acc.real();
        }
    double inv = 1.0/sqrt(nrm2);
    for (int j = 0; j < d1; j++)
      for (int lq = 0; lq < d2; lq++)
        for (int n = 0; n < d3; n++) W[j][lq][n] *= inv;
}

static const int H_PL[15][3] = {{0,0,0},{1,1,0},{2,2,0},{0,1,1},{1,0,1},{1,1,1},
                                {1,2,1},{2,1,1},{2,2,1},{0,2,2},{2,0,2},{1,1,2},
                                {1,2,2},{2,1,2},{2,2,2}};
static const int H_W3OFF[15] = {0,1,10,35,44,53,80,125,170,245,270,295,340,415,490};

static void h_build_params(QParams& qp, FoldParams& fp){
    float w3[615];
    const double alpha[3] = { sqrt(1.0/768.0), sqrt(3.0/1536.0), sqrt(5.0/1536.0) };
    for (int p = 0; p < 15; p++) {
        int l1 = H_PL[p][0], l2 = H_PL[p][1], lo = H_PL[p][2];
        double W[5][5][5];
        h_wigner3j(l1,l2,lo,W);
        int jd = 2*l2+1, kd = 2*lo+1;
        for (int i = 0; i < 2*l1+1; i++)
          for (int j = 0; j < jd; j++)
            for (int k = 0; k < kd; k++)
                w3[H_W3OFF[p] + (i*jd+j)*kd + k] = (float)(alpha[lo]*W[i][j][k]);
    }
    int ko = 0;
    for (int l = 0; l <= 2; l++) {
        double W[5][5][5];
        h_wigner3j(1,1,l,W);
        double s = sqrt(2.0*l+1.0);
        for (int m = 0; m < 2*l+1; m++)
          for (int i = 0; i < 3; i++)
            for (int j = 0; j < 3; j++)
                qp.q[(ko+m)*9 + i*3 + j] = (float)(s*W[i][j][m]);
        ko += 2*l+1;
    }
    // cell-ordered fold coefficients, slices padded to multiples of 4.
    // cell order: lo-major (lo,l2) = (0,0)(0,1)(0,2)(1,0)(1,1)(1,2)(2,0)(2,1)(2,2)
    int nt = 0;
    for (int lo = 0; lo < 3; lo++) {
        const int kd = 2*lo+1;
        for (int l2 = 0; l2 < 3; l2++) {
            const int jd = 2*l2+1;
            const int S = (jd*kd + 3) & ~3;
            for (int p = 0; p < 15; p++) {
                if (H_PL[p][1] != l2 || H_PL[p][2] != lo) continue;
                for (int i = 0; i < 2*H_PL[p][0]+1; i++) {
                    for (int lin = 0; lin < S; lin++) {
                        if (lin < jd*kd) {
                            const int j = lin / kd, k = lin % kd;
                            fp.cf[nt++] = w3[H_W3OFF[p] + (i*jd + j)*kd + k];
                        } else fp.cf[nt++] = 0.0f;
                    }
                }
            }
        }
    }
    // nt == 724
}

// ==================================================================
extern "C" void kernel_launch(void* const* d_in, const int* in_sizes, int n_in,
                              void* d_out, int out_size)
{
    const float* feats = nullptr;
    const float* tpw   = nullptr;
    for (int i = 0; i < n_in; i++) {
        if (in_sizes[i] == NNODES*144)   feats = (const float*)d_in[i];
        else if (in_sizes[i] == 15*256)  tpw   = (const float*)d_in[i];
    }
    QParams qp; FoldParams fp;
    h_build_params(qp, fp);

    cudaFuncSetAttribute(k1_buildC, cudaFuncAttributeMaxDynamicSharedMemorySize, SMEM_K1);
    cudaFuncSetAttribute(k3_pairs,  cudaFuncAttributeMaxDynamicSharedMemorySize, SMEM_K3);
    cudaFuncSetAttribute(k4_cart,   cudaFuncAttributeMaxDynamicSharedMemorySize, SMEM_K4);

    k1_buildC<<<NNODES/8, 128, SMEM_K1>>>(feats, tpw, fp);
    k3_pairs<<<NCFG*2, 512, SMEM_K3>>>(feats);
    k4_cart<<<NCFG*4, 256, SMEM_K4>>>((float*)d_out, qp);
}

// round 17
// speedup vs baseline: 1.3873x; 1.1474x over previous
#include <cuda_runtime.h>
#include <cuda_bf16.h>
#include <math.h>
#include <complex>
#include <algorithm>

// ---------------- static problem shape ----------------
#define MUL    16
#define NCFG   64
#define NATOM  64
#define NNODES 4096
#define NPAIRS 262144

// ---------------- device scratch (no allocation allowed) ----------------
// planar irr: g_irr[k*NPAIRS + e]
__device__ float g_irr[(size_t)9 * NPAIRS];

struct QParams  { float q[81];  };   // QCART[k][3][3]
struct FoldParams { float cf[724]; };// cell-ordered fold coefficients (slices padded to 4)

// ---------------- f32x2 packed-math helpers ----------------
typedef unsigned long long u64t;
__device__ __forceinline__ u64t pk2(float lo, float hi){
    u64t r; asm("mov.b64 %0, {%1,%2};" : "=l"(r) : "f"(lo), "f"(hi)); return r;
}
__device__ __forceinline__ void fma2(u64t &d, u64t a, u64t b){
    asm("fma.rn.f32x2 %0, %1, %2, %0;" : "+l"(d) : "l"(a), "l"(b));
}
__device__ __forceinline__ void upk2(float &lo, float &hi, u64t v){
    asm("mov.b64 {%0,%1}, %2;" : "=f"(lo), "=f"(hi) : "l"(v));
}
__device__ __forceinline__ float dot4(float4 a, float4 b){
    return a.x*b.x + a.y*b.y + a.z*b.z + a.w*b.w;
}

// ==================================================================
// Fused K3: per-block C build (ex-K1) + pair stage.
// Grid 128 = (cfg, rowhalf rg), 512 threads.
// smem (float offsets):
//   Cs    @0       16 np x 2592        (165888 B)
//   union @41472:
//     build:  wsT [15*320]=4800 | cfS [724] | xT [32*148]=4736  (10260 fl)
//     pairs:  Xs  [64*148]=9472 fl
// total 51732 fl = 206928 B -> 1 block/SM, 16 warps.
// ==================================================================
#define CS_STRIDE 2592
#define U_OFF     41472
#define SMEM_K3   (51732 * 4)

// one (lo,l2) cell for one (node, v): accumulate out[jd*kd] scalar f32,
// write pair-interleaved into Cs chunk. CKG0 = absolute kg base (0/1/4).
template<int L2, int LO, int NP, int P0, int P1, int P2, int CFB, int CKG0>
__device__ __forceinline__ void do_cell(const float* __restrict__ xb,
                                        const float* __restrict__ wsT,
                                        const float* __restrict__ cfS,
                                        float* __restrict__ cst,
                                        const int v)
{
    constexpr int jd = 2*L2+1, kd = 2*LO+1;
    constexpr int S  = (jd*kd + 3) & ~3;
    constexpr int PLL[3] = {P0, P1, P2};
    constexpr int PD [15] = {1,3,5,1,3,3,3,5,5,1,5,3,3,5,5};
    constexpr int PFB[15] = {0,16,64,0,16,16,16,64,64,0,64,16,16,64,64};
    constexpr int L2B[3] = {0,16,64};

    float out[jd*kd];
    #pragma unroll
    for (int q = 0; q < jd*kd; q++) out[q] = 0.f;

    int slice = 0;
    #pragma unroll
    for (int pp = 0; pp < NP; pp++) {
        const int p = PLL[pp];
        const float4* w4 = (const float4*)(wsT + p*320 + v*20);
        const float4 w0 = w4[0], w1 = w4[1], w2 = w4[2], w3v = w4[3];
        #pragma unroll
        for (int i = 0; i < PD[PLL[pp]]; i++) {
            const float4* xr = (const float4*)(xb + PFB[PLL[pp]] + i*16);
            const float t = dot4(w0,xr[0]) + dot4(w1,xr[1])
                          + dot4(w2,xr[2]) + dot4(w3v,xr[3]);
            const int co = CFB + slice*S;
            #pragma unroll
            for (int g = 0; g < S/4; g++) {
                const float4 c4 = *(const float4*)(cfS + co + g*4);
                const float cc[4] = {c4.x, c4.y, c4.z, c4.w};
                #pragma unroll
                for (int l = 0; l < 4; l++) {
                    constexpr int JK = jd*kd;
                    const int lin = g*4 + l;
                    if (lin < JK) out[lin] += cc[l]*t;
                }
            }
            slice++;
        }
    }
    #pragma unroll
    for (int j = 0; j < jd; j++)
        #pragma unroll
        for (int k = 0; k < kd; k++)
            cst[((CKG0 + k)*144 + L2B[L2] + v*jd + j)*2] = out[j*kd + k];
}

__global__ __launch_bounds__(512, 1) void k3_fused(const float* __restrict__ feats,
                                                   const float* __restrict__ tpw,
                                                   FoldParams fp)
{
    extern __shared__ float sm[];
    float* Cs  = sm;                 // [16 np][2592]
    float* wsT = sm + U_OFF;         // build phase
    float* cfS = sm + U_OFF + 4800;
    float* xT  = sm + U_OFF + 5524;  // [32][148]
    float* Xs  = sm + U_OFF;         // pair phase overlay [64][148]
    const int tid = threadIdx.x;
    const int cfg = blockIdx.x >> 1;
    const int rg  = blockIdx.x & 1;
    const int rowbase = cfg*64 + rg*32;   // first of 32 row-nodes this block builds

    // ---- phase 1 loads: weights, fold coeffs, row feats (transposed) ----
    for (int idx = tid; idx < 3840; idx += 512) {
        const int p = idx >> 8, r = idx & 255, u = r >> 4, vv = r & 15;
        wsT[p*320 + vv*20 + u] = tpw[idx];
    }
    for (int idx = tid; idx < 32*144; idx += 512) {
        const int n = idx / 144, f = idx - n*144;
        int off;
        if (f < 16)      { off = f; }
        else if (f < 64) { int g = f-16; int u = g/3; off = 16 + (g-3*u)*16 + u; }
        else             { int g = f-64; int u = g/5; off = 64 + (g-5*u)*16 + u; }
        xT[n*148 + off] = feats[(size_t)rowbase*144 + idx];
    }
    for (int idx = tid; idx < 724; idx += 512) cfS[idx] = fp.cf[idx];
    __syncthreads();

    // ---- build C: thread = (nl = tid>>4 node 0..31, v = tid&15) ----
    {
        const int nl = tid >> 4;
        const int v  = tid & 15;
        const float* xb = xT + nl*148;
        float* cst = Cs + (nl >> 1)*CS_STRIDE + (nl & 1);

        do_cell<0,0,1,  0, 0, 0,   0, 0>(xb, wsT, cfS, cst, v);   // c00
        do_cell<1,0,1,  1, 0, 0,   4, 0>(xb, wsT, cfS, cst, v);   // c01
        do_cell<2,0,1,  2, 0, 0,  16, 0>(xb, wsT, cfS, cst, v);   // c02
        do_cell<0,1,1,  4, 0, 0,  56, 1>(xb, wsT, cfS, cst, v);   // c10
        do_cell<1,1,3,  3, 5, 7,  68, 1>(xb, wsT, cfS, cst, v);   // c11
        do_cell<2,1,2,  6, 8, 0, 176, 1>(xb, wsT, cfS, cst, v);   // c12
        do_cell<0,2,1, 10, 0, 0, 304, 4>(xb, wsT, cfS, cst, v);   // c20
        do_cell<1,2,2, 11,13, 0, 344, 4>(xb, wsT, cfS, cst, v);   // c21
        do_cell<2,2,3,  9,12,14, 472, 4>(xb, wsT, cfS, cst, v);   // c22
    }
    __syncthreads();

    // ---- phase 2 load: col feats (overwrites build buffers) ----
    {
        const float4* src = (const float4*)(feats + (size_t)cfg*9216);
        for (int idx = tid; idx < 2304; idx += 512) {
            const int col = idx / 36, q = idx - col*36;
            *(float4*)(Xs + col*148 + q*4) = src[idx];
        }
    }
    __syncthreads();

    // ---- pair loop (R9-exact; Cs stride 2592) ----
    const int rp = tid >> 5;
    const int cg = tid & 31;
    const float* Crow = Cs + rp*CS_STRIDE;

    u64t acc[2][9];
    #pragma unroll
    for (int c = 0; c < 2; c++)
        #pragma unroll
        for (int k = 0; k < 9; k++) acc[c][k] = 0ULL;

    #pragma unroll 2
    for (int q = 0; q < 36; q++) {
        const float4 xv0 = *(const float4*)(Xs + cg*148 + q*4);
        const float4 xv1 = *(const float4*)(Xs + (cg+32)*148 + q*4);
        u64t xp0[4], xp1[4];
        xp0[0] = pk2(xv0.x, xv0.x); xp0[1] = pk2(xv0.y, xv0.y);
        xp0[2] = pk2(xv0.z, xv0.z); xp0[3] = pk2(xv0.w, xv0.w);
        xp1[0] = pk2(xv1.x, xv1.x); xp1[1] = pk2(xv1.y, xv1.y);
        xp1[2] = pk2(xv1.z, xv1.z); xp1[3] = pk2(xv1.w, xv1.w);
        #pragma unroll
        for (int k = 0; k < 9; k++) {
            const double2* cp = (const double2*)(Crow + (k*144 + q*4)*2);
            const double2 d0 = cp[0], d1 = cp[1];
            const u64t c0 = __double_as_longlong(d0.x);
            const u64t c1 = __double_as_longlong(d0.y);
            const u64t c2 = __double_as_longlong(d1.x);
            const u64t c3 = __double_as_longlong(d1.y);
            fma2(acc[0][k], c0, xp0[0]); fma2(acc[0][k], c1, xp0[1]);
            fma2(acc[0][k], c2, xp0[2]); fma2(acc[0][k], c3, xp0[3]);
            fma2(acc[1][k], c0, xp1[0]); fma2(acc[1][k], c1, xp1[1]);
            fma2(acc[1][k], c2, xp1[2]); fma2(acc[1][k], c3, xp1[3]);
        }
    }

    const int row0 = rg*32 + 2*rp;
    const int e0 = cfg*4096 + row0*64 + cg;
    #pragma unroll
    for (int c = 0; c < 2; c++) {
        const int ec = e0 + c*32;
        #pragma unroll
        for (int k = 0; k < 9; k++) {
            float lo, hi; upk2(lo, hi, acc[c][k]);
            g_irr[(size_t)k*NPAIRS + ec]      = lo;
            g_irr[(size_t)k*NPAIRS + ec + 64] = hi;
        }
    }
}

// ==================================================================
// K4: cartesian change of basis + symmetrize; smem transpose tiles.
// Block = (cfg, 2x2 quadrant of 32x32 pairs): grid 256, 256 threads. (R9-exact)
// ==================================================================
#define K4_A    0
#define K4_B    9216
#define K4_O    (9216 + 9504)
#define SMEM_K4 ((9216 + 9504 + 2304) * 4)

__global__ __launch_bounds__(256) void k4_cart(float* __restrict__ out, QParams qp)
{
    extern __shared__ float sm4[];
    float* A = sm4 + K4_A;
    float* B = sm4 + K4_B;
    float* obuf = sm4 + K4_O;
    const int tid = threadIdx.x;
    const int cfg = blockIdx.x >> 2;
    const int ib  = (blockIdx.x >> 1) & 1;
    const int jb  = blockIdx.x & 1;
    const int ebase = cfg*4096;

    for (int idx = tid; idx < 9216; idx += 256) {
        const int k = idx >> 10, p = idx & 1023, r = p >> 5, c = p & 31;
        A[idx] = g_irr[(size_t)k*NPAIRS + ebase + (ib*32+r)*64 + jb*32 + c];
        B[k*1056 + r*33 + c] =
            g_irr[(size_t)k*NPAIRS + ebase + (jb*32+r)*64 + ib*32 + c];
    }
    __syncthreads();

    for (int s = 0; s < 4; s++) {
        const int p = s*256 + tid;
        const int r = p >> 5, c = p & 31;
        float a[9], ap[9];
        #pragma unroll
        for (int k = 0; k < 9; k++) {
            a[k]  = A[k*1024 + p];
            ap[k] = B[k*1056 + c*33 + r];
        }
        #pragma unroll
        for (int ii = 0; ii < 3; ii++)
            #pragma unroll
            for (int jj = 0; jj < 3; jj++) {
                float sacc = 0.f;
                #pragma unroll
                for (int k = 0; k < 9; k++)
                    sacc += a[k]*qp.q[k*9 + ii*3 + jj] + ap[k]*qp.q[k*9 + jj*3 + ii];
                obuf[tid*9 + ii*3 + jj] = 0.5f * sacc;
            }
        __syncthreads();
        for (int idx = tid; idx < 576; idx += 256) {
            const int rl = idx / 72, q = idx - rl*72;
            ((float4*)(out + (size_t)(ebase + (ib*32 + s*8 + rl)*64 + jb*32)*9))[q] =
                ((const float4*)(obuf + rl*288))[q];
        }
        __syncthreads();
    }
}

// ==================================================================
// Host: real Wigner-3j (e3nn convention) + QCART + fold tables, per call.
// ==================================================================
static double h_fact(int n){ double r=1; for(int i=2;i<=n;i++) r*=i; return r; }

static double h_su2_cg(int j1,int m1,int j2,int m2,int j3,int m3){
    if (m3 != m1+m2) return 0.0;
    int vmin = std::max(std::max(-j1+j2+m3, -j1+m1), 0);
    int vmax = std::min(std::min(j2+j3+m1, j3-j1+j2), j3+m3);
    double C = sqrt((2.0*j3+1)*h_fact(j3+j1-j2)*h_fact(j3-j1+j2)*h_fact(j1+j2-j3)
               *h_fact(j3+m3)*h_fact(j3-m3)
               /(h_fact(j1+j2+j3+1)*h_fact(j1-m1)*h_fact(j1+m1)*h_fact(j2-m2)*h_fact(j2+m2)));
    double S = 0.0;
    for (int v = vmin; v <= vmax; v++) {
        double term = h_fact(j2+j3+m1-v)*h_fact(j1-m1+v)
                    /(h_fact(v)*h_fact(j3-j1+j2-v)*h_fact(j3+m3-v)*h_fact(v+j1-j2-m3));
        S += (((v+j2+m2) & 1) ? -1.0 : 1.0) * term;
    }
    return C*S;
}

typedef std::complex<double> cd;

static void h_qmat(int l, cd Q[5][5]){
    for (int i = 0; i < 5; i++) for (int j = 0; j < 5; j++) Q[i][j] = cd(0,0);
    const double s = 1.0/sqrt(2.0);
    for (int m = -l; m < 0; m++) {
        Q[l+m][l-m] = cd(s,0);
        Q[l+m][l+m] = cd(0,-s);
    }
    Q[l][l] = cd(1,0);
    for (int m = 1; m <= l; m++) {
        double sg = (m & 1) ? -1.0 : 1.0;
        Q[l+m][l+m] = cd(sg*s, 0);
        Q[l+m][l-m] = cd(0, sg*s);
    }
    cd f = (l==0) ? cd(1,0) : (l==1) ? cd(0,-1) : cd(-1,0);
    for (int i = 0; i < 5; i++) for (int j = 0; j < 5; j++) Q[i][j] *= f;
}

static void h_wigner3j(int l1,int l2,int l3, double W[5][5][5]){
    int d1 = 2*l1+1, d2 = 2*l2+1, d3 = 2*l3+1;
    double C[5][5][5] = {};
    for (int m1 = -l1; m1 <= l1; m1++)
        for (int m2 = -l2; m2 <= l2; m2++) {
            int m3 = m1+m2;
            if (m3 >= -l3 && m3 <= l3)
                C[l1+m1][l2+m2][l3+m3] = h_su2_cg(l1,m1,l2,m2,l3,m3);
        }
    cd Q1[5][5], Q2[5][5], Q3[5][5];
    h_qmat(l1,Q1); h_qmat(l2,Q2); h_qmat(l3,Q3);
    double nrm2 = 0.0;
    for (int j = 0; j < d1; j++)
      for (int lq = 0; lq < d2; lq++)
        for (int n = 0; n < d3; n++) {
            cd acc(0,0);
            for (int i = 0; i < d1; i++)
              for (int k = 0; k < d2; k++)
                for (int m = 0; m < d3; m++) {
                    double c = C[i][k][m];
                    if (c != 0.0) acc += Q1[i][j]*Q2[k][lq]*std::conj(Q3[m][n])*c;
                }
            W[j][lq][n] = acc.real();
            nrm2 += acc.real()*acc.real();
        }
    double inv = 1.0/sqrt(nrm2);
    for (int j = 0; j < d1; j++)
      for (int lq = 0; lq < d2; lq++)
        for (int n = 0; n < d3; n++) W[j][lq][n] *= inv;
}

static const int H_PL[15][3] = {{0,0,0},{1,1,0},{2,2,0},{0,1,1},{1,0,1},{1,1,1},
                                {1,2,1},{2,1,1},{2,2,1},{0,2,2},{2,0,2},{1,1,2},
                                {1,2,2},{2,1,2},{2,2,2}};
static const int H_W3OFF[15] = {0,1,10,35,44,53,80,125,170,245,270,295,340,415,490};

static void h_build_params(QParams& qp, FoldParams& fp){
    float w3[615];
    const double alpha[3] = { sqrt(1.0/768.0), sqrt(3.0/1536.0), sqrt(5.0/1536.0) };
    for (int p = 0; p < 15; p++) {
        int l1 = H_PL[p][0], l2 = H_PL[p][1], lo = H_PL[p][2];
        double W[5][5][5];
        h_wigner3j(l1,l2,lo,W);
        int jd = 2*l2+1, kd = 2*lo+1;
        for (int i = 0; i < 2*l1+1; i++)
          for (int j = 0; j < jd; j++)
            for (int k = 0; k < kd; k++)
                w3[H_W3OFF[p] + (i*jd+j)*kd + k] = (float)(alpha[lo]*W[i][j][k]);
    }
    int ko = 0;
    for (int l = 0; l <= 2; l++) {
        double W[5][5][5];
        h_wigner3j(1,1,l,W);
        double s = sqrt(2.0*l+1.0);
        for (int m = 0; m < 2*l+1; m++)
          for (int i = 0; i < 3; i++)
            for (int j = 0; j < 3; j++)
                qp.q[(ko+m)*9 + i*3 + j] = (float)(s*W[i][j][m]);
        ko += 2*l+1;
    }
    // cell-ordered fold coefficients, slices padded to multiples of 4.
    // cell order: lo-major (lo,l2) = (0,0)(0,1)(0,2)(1,0)(1,1)(1,2)(2,0)(2,1)(2,2)
    int nt = 0;
    for (int lo = 0; lo < 3; lo++) {
        const int kd = 2*lo+1;
        for (int l2 = 0; l2 < 3; l2++) {
            const int jd = 2*l2+1;
            const int S = (jd*kd + 3) & ~3;
            for (int p = 0; p < 15; p++) {
                if (H_PL[p][1] != l2 || H_PL[p][2] != lo) continue;
                for (int i = 0; i < 2*H_PL[p][0]+1; i++) {
                    for (int lin = 0; lin < S; lin++) {
                        if (lin < jd*kd) {
                            const int j = lin / kd, k = lin % kd;
                            fp.cf[nt++] = w3[H_W3OFF[p] + (i*jd + j)*kd + k];
                        } else fp.cf[nt++] = 0.0f;
                    }
                }
            }
        }
    }
    // nt == 724
}

// ==================================================================
extern "C" void kernel_launch(void* const* d_in, const int* in_sizes, int n_in,
                              void* d_out, int out_size)
{
    const float* feats = nullptr;
    const float* tpw   = nullptr;
    for (int i = 0; i < n_in; i++) {
        if (in_sizes[i] == NNODES*144)   feats = (const float*)d_in[i];
        else if (in_sizes[i] == 15*256)  tpw   = (const float*)d_in[i];
    }
    QParams qp; FoldParams fp;
    h_build_params(qp, fp);

    cudaFuncSetAttribute(k3_fused, cudaFuncAttributeMaxDynamicSharedMemorySize, SMEM_K3);
    cudaFuncSetAttribute(k4_cart,  cudaFuncAttributeMaxDynamicSharedMemorySize, SMEM_K4);

    k3_fused<<<NCFG*2, 512, SMEM_K3>>>(feats, tpw, fp);
    k4_cart<<<NCFG*4, 256, SMEM_K4>>>((float*)d_out, qp);
}